// round 15
// baseline (speedup 1.0000x reference)
#include <cuda_runtime.h>
#include <cuda_fp16.h>
#include <cstdint>

// ---------------------------------------------------------------------------
// GCN via mma.sync fp16 GEMMs (fp32 accumulate).
//   GEMM1 (fused cvt): H^T = W^T @ X^T, X fp32 converted in smem -> H^T fp16
//   GEMM2: Out[b] = adj @ H_b, PAIRED: one CTA does both n-tiles through one
//          continuous cp.async ring (single wave: 256 CTAs on 296 slots).
// R15: coalesced tiled w-transpose; GEMM2 n-pairing with compile-time shifts.
// ---------------------------------------------------------------------------

#define N_NODES 512
#define N_BATCH 64
#define D_IN    256
#define D_OUT   256
#define M_ALL   (N_NODES * N_BATCH)   // 32768

// ---- GEMM2 config (R8 inner loop) ----
#define BM 128
#define BN 128
#define BKB 64
#define NTHREADS 256
#define S_STAGES 3
#define PITCHB 144
#define TILEB (128 * PITCHB)
#define STAGEB (2 * TILEB)
#define SMEM_TOTAL (S_STAGES * STAGEB) // 110592
#define OFF_A 0
#define OFF_B TILEB

// ---- GEMM1 fused config (BK=32 fp16) ----
#define G1_PITCH_A   80
#define G1_PITCH_B32 144
#define G1_A_STAGE   (128 * G1_PITCH_A)   // 10240
#define G1_B32_STAGE (128 * G1_PITCH_B32) // 18432
#define G1_OFF_A     0
#define G1_OFF_B32   (3 * G1_A_STAGE)
#define G1_OFF_B16   (G1_OFF_B32 + 3 * G1_B32_STAGE)
#define G1_SMEM      (G1_OFF_B16 + 2 * G1_A_STAGE)       // 106496

// device scratch
__device__ __half g_wth[D_OUT * D_IN];
__device__ __half g_adjh[N_NODES * N_NODES];
__device__ __half g_h[(size_t)D_OUT * M_ALL];

// ---------------- helpers ----------------
__device__ __forceinline__ uint32_t smem_u32(const void* p) {
    uint32_t a;
    asm("{ .reg .u64 t; cvta.to.shared.u64 t, %1; cvt.u32.u64 %0, t; }" : "=r"(a) : "l"(p));
    return a;
}
__device__ __forceinline__ void cp16(uint32_t dst, const void* src) {
    asm volatile("cp.async.cg.shared.global [%0], [%1], 16;" :: "r"(dst), "l"(src) : "memory");
}
__device__ __forceinline__ void cp_commit() {
    asm volatile("cp.async.commit_group;" ::: "memory");
}
template <int N>
__device__ __forceinline__ void cp_wait() {
    asm volatile("cp.async.wait_group %0;" :: "n"(N) : "memory");
}
__device__ __forceinline__ void ldsm_x4(uint32_t* r, uint32_t addr) {
    asm volatile("ldmatrix.sync.aligned.m8n8.x4.shared.b16 {%0,%1,%2,%3}, [%4];"
                 : "=r"(r[0]), "=r"(r[1]), "=r"(r[2]), "=r"(r[3]) : "r"(addr));
}
__device__ __forceinline__ void mma_f16(float* c, const uint32_t* a, const uint32_t* b) {
    asm volatile(
        "mma.sync.aligned.m16n8k16.row.col.f32.f16.f16.f32 "
        "{%0,%1,%2,%3}, {%4,%5,%6,%7}, {%8,%9}, {%0,%1,%2,%3};"
        : "+f"(c[0]), "+f"(c[1]), "+f"(c[2]), "+f"(c[3])
        : "r"(a[0]), "r"(a[1]), "r"(a[2]), "r"(a[3]), "r"(b[0]), "r"(b[1]));
}
__device__ __forceinline__ uint2 cvt_f4(float4 a) {
    __half2 h0 = __float22half2_rn(make_float2(a.x, a.y));
    __half2 h1 = __float22half2_rn(make_float2(a.z, a.w));
    return make_uint2(*(uint32_t*)&h0, *(uint32_t*)&h1);
}

// ---------------- convert kernel: adj (flat) + w (tiled transpose) ---------
// blocks [0,64): adj convert (MLP=4 flat)
// blocks [64,128): w transpose+convert, 32x32 smem tiles, coalesced both ways
__global__ __launch_bounds__(256) void cvt_small(const float* __restrict__ adj,
                                                 const float* __restrict__ w,
                                                 __half* __restrict__ adjh,
                                                 __half* __restrict__ wth) {
    const int b = blockIdx.x;
    if (b < 64) {
        const size_t t = (size_t)b * 256 + threadIdx.x;
        const float4* src = (const float4*)adj + t * 4;
        float4 v0 = src[0], v1 = src[1], v2 = src[2], v3 = src[3];
        uint2 a0 = cvt_f4(v0), a1 = cvt_f4(v1), a2 = cvt_f4(v2), a3 = cvt_f4(v3);
        uint4* dst = (uint4*)adjh + t * 2;
        dst[0] = make_uint4(a0.x, a0.y, a1.x, a1.y);
        dst[1] = make_uint4(a2.x, a2.y, a3.x, a3.y);
    } else {
        __shared__ __half sm[32][33];
        const int tb = b - 64;          // 0..63
        const int bx = tb & 7;          // col tile of w
        const int by = tb >> 3;         // row tile of w
        const int tx = threadIdx.x & 31;
        const int ty = threadIdx.x >> 5;   // 0..7
        // coalesced read of w tile [by*32 .. +32) x [bx*32 .. +32)
#pragma unroll
        for (int j = 0; j < 4; j++) {
            int r = ty + j * 8;
            sm[r][tx] = __float2half_rn(w[(size_t)(by * 32 + r) * D_OUT + bx * 32 + tx]);
        }
        __syncthreads();
        // coalesced write of wth tile: wth[o][i] = w[i][o]
#pragma unroll
        for (int j = 0; j < 4; j++) {
            int r = ty + j * 8;
            wth[(size_t)(bx * 32 + r) * D_IN + by * 32 + tx] = sm[tx][r];
        }
    }
}

// ---------------- GEMM1 fused: H^T = W^T @ X^T, X fp32 in-flight ----------
__global__ __launch_bounds__(NTHREADS, 2)
void gemm1_fused(const __half* __restrict__ A,
                 const float* __restrict__ X,
                 __half* __restrict__ Ch) {
    extern __shared__ char smem[];
    const uint32_t sb = smem_u32(smem);
    const int tid = threadIdx.x;
    const int lane = tid & 31;
    const int wid = tid >> 5;
    const int wm = (wid & 3) * 32;
    const int wn = (wid >> 2) * 64;

    const int m0 = blockIdx.y * BM;
    const int n0 = blockIdx.x * BN;

    const int arow = tid >> 2;
    const int acol = tid & 3;
    const int brow = tid >> 3;
    const int bcol = tid & 7;
    const int vrow = tid >> 1;
    const int vcol = (tid & 1) * 2;

    const uint32_t aOff = (uint32_t)((wm + (lane & 15)) * G1_PITCH_A + ((lane >> 4) << 4));
    const uint32_t bOff = (uint32_t)((wn + ((lane >> 4) << 3) + (lane & 7)) * G1_PITCH_A +
                                     (((lane >> 3) & 1) << 4));

    float acc[2][8][4];
#pragma unroll
    for (int mt = 0; mt < 2; mt++)
#pragma unroll
        for (int nt = 0; nt < 8; nt++)
#pragma unroll
            for (int q = 0; q < 4; q++) acc[mt][nt][q] = 0.0f;

    const int NT = D_IN / 32;   // 8 stages

    auto load_stage = [&](int s) {
        const uint32_t stA = sb + G1_OFF_A + (uint32_t)((s % 3) * G1_A_STAGE);
        const uint32_t stB = sb + G1_OFF_B32 + (uint32_t)((s % 3) * G1_B32_STAGE);
        const int k16 = s * 32;
#pragma unroll
        for (int j = 0; j < 2; j++) {
            int r = arow + j * 64;
            cp16(stA + (uint32_t)(r * G1_PITCH_A + acol * 16),
                 A + (size_t)(m0 + r) * D_IN + k16 + acol * 8);
        }
#pragma unroll
        for (int j = 0; j < 4; j++) {
            int r = brow + j * 32;
            cp16(stB + (uint32_t)(r * G1_PITCH_B32 + bcol * 16),
                 X + (size_t)(n0 + r) * D_IN + k16 + bcol * 4);
        }
        cp_commit();
    };

    load_stage(0);
    load_stage(1);

    for (int t = 0; t < NT; t++) {
        cp_wait<1>();
        __syncthreads();

        const uint32_t srcB = sb + G1_OFF_B32 + (uint32_t)((t % 3) * G1_B32_STAGE);
        const uint32_t dstB = sb + G1_OFF_B16 + (uint32_t)((t & 1) * G1_A_STAGE);
#pragma unroll
        for (int j = 0; j < 2; j++) {
            int oc = vcol + j;
            float4 f0 = *(const float4*)(smem + (srcB - sb) + vrow * G1_PITCH_B32 + oc * 32);
            float4 f1 = *(const float4*)(smem + (srcB - sb) + vrow * G1_PITCH_B32 + oc * 32 + 16);
            uint2 p0 = cvt_f4(f0);
            uint2 p1 = cvt_f4(f1);
            *(uint4*)(smem + (dstB - sb) + vrow * G1_PITCH_A + oc * 16) =
                make_uint4(p0.x, p0.y, p1.x, p1.y);
        }
        __syncthreads();

        const uint32_t stA = sb + G1_OFF_A + (uint32_t)((t % 3) * G1_A_STAGE);
#pragma unroll
        for (int ko = 0; ko < 2; ko++) {
            uint32_t ah[2][4];
#pragma unroll
            for (int mt = 0; mt < 2; mt++)
                ldsm_x4(ah[mt], stA + aOff + mt * 16 * G1_PITCH_A + ko * 32);
#pragma unroll
            for (int np = 0; np < 4; np++) {
                uint32_t bh[4];
                ldsm_x4(bh, dstB + bOff + np * 16 * G1_PITCH_A + ko * 32);
#pragma unroll
                for (int sub = 0; sub < 2; sub++)
#pragma unroll
                    for (int mt = 0; mt < 2; mt++)
                        mma_f16(acc[mt][np * 2 + sub], ah[mt], bh + sub * 2);
            }
        }

        if (t + 2 < NT) {
            load_stage(t + 2);
        } else {
            cp_commit();
        }
    }

    const int l4 = lane >> 2;
    const int lp = lane & 3;
#pragma unroll
    for (int mt = 0; mt < 2; mt++) {
#pragma unroll
        for (int nt = 0; nt < 8; nt++) {
            const float* c = acc[mt][nt];
            long m = m0 + wm + mt * 16 + l4;
            long n = n0 + wn + nt * 8 + lp * 2;
            __half2 p0 = __float22half2_rn(make_float2(c[0], c[1]));
            __half2 p1 = __float22half2_rn(make_float2(c[2], c[3]));
            *(uint32_t*)(Ch + m * M_ALL + n) = *(uint32_t*)&p0;
            *(uint32_t*)(Ch + (m + 8) * M_ALL + n) = *(uint32_t*)&p1;
        }
    }
}

// ---------------- GEMM2 paired: Out[b] = adj @ H_b, 2 n-tiles per CTA ------
// K=512, BK=64: NTIN=8 stages per tile, 2 tiles -> 16 stages continuous.
// tile = s>>3 (compile-time shift), A (adj) identical across tiles.
#define G2_NTIN 8
#define G2_NS   16
__global__ __launch_bounds__(NTHREADS, 2)
void gemm2_paired(const __half* __restrict__ A,      // adj fp16 [512][512]
                  const __half* __restrict__ B,      // H^T [256][32768]
                  float* __restrict__ Cf) {          // out [32768][256]
    extern __shared__ char smem[];
    const uint32_t sb = smem_u32(smem);
    const int tid = threadIdx.x;
    const int lane = tid & 31;
    const int wid = tid >> 5;
    const int wm = (wid & 3) * 32;
    const int wn = (wid >> 2) * 64;

    const int m0 = blockIdx.y * BM;              // node-row tile in batch
    const long bz = blockIdx.z;                  // batch
    B  += bz * (long)N_NODES;                    // H^T column slice
    Cf += bz * (long)(N_NODES * D_OUT);

    const int cr = tid >> 3;
    const int cc = tid & 7;
    const uint32_t soBase = (uint32_t)(cc * 16);
    const int gcol = cc * 8;

    const uint32_t aOff = (uint32_t)((wm + (lane & 15)) * PITCHB + ((lane >> 4) << 4));
    const uint32_t bOff = (uint32_t)((wn + ((lane >> 4) << 3) + (lane & 7)) * PITCHB +
                                     (((lane >> 3) & 1) << 4));

    float acc[2][8][4];
#pragma unroll
    for (int mt = 0; mt < 2; mt++)
#pragma unroll
        for (int nt = 0; nt < 8; nt++)
#pragma unroll
            for (int q = 0; q < 4; q++) acc[mt][nt][q] = 0.0f;

    auto load_stage = [&](int s) {
        const int tile = s >> 3;                 // 0 or 1: n-tile (dout 0 / 128)
        const int t = s & 7;
        const uint32_t st = sb + (uint32_t)((s % S_STAGES) * STAGEB);
        const int k0 = t * BKB + gcol;
        const __half* Bt = B + (size_t)tile * BN * M_ALL;   // dout rows offset
#pragma unroll
        for (int j = 0; j < 4; j++) {
            int r = cr + j * 32;
            uint32_t so = (uint32_t)(r * PITCHB) + soBase;
            cp16(st + OFF_A + so, A + (size_t)(m0 + r) * N_NODES + k0);
            cp16(st + OFF_B + so, Bt + (size_t)r * M_ALL + k0);
        }
        cp_commit();
    };

    load_stage(0);
    load_stage(1);

    const int l4 = lane >> 2;
    const int lp = lane & 3;

    for (int s = 0; s < G2_NS; s++) {
        cp_wait<1>();
        __syncthreads();

        const uint32_t st = sb + (uint32_t)((s % S_STAGES) * STAGEB);

        uint32_t ah[2][2][4];
#pragma unroll
        for (int mt = 0; mt < 2; mt++)
            ldsm_x4(ah[0][mt], st + OFF_A + aOff + mt * 16 * PITCHB);

#pragma unroll
        for (int ko = 0; ko < 4; ko++) {
            const int cur = ko & 1, nxt = cur ^ 1;
            if (ko < 3) {
#pragma unroll
                for (int mt = 0; mt < 2; mt++)
                    ldsm_x4(ah[nxt][mt], st + OFF_A + aOff + mt * 16 * PITCHB + (ko + 1) * 32);
            }
#pragma unroll
            for (int np = 0; np < 4; np++) {
                uint32_t bh[4];
                ldsm_x4(bh, st + OFF_B + bOff + np * 16 * PITCHB + ko * 32);
#pragma unroll
                for (int sub = 0; sub < 2; sub++)
#pragma unroll
                    for (int mt = 0; mt < 2; mt++)
                        mma_f16(acc[mt][np * 2 + sub], ah[cur][mt], bh + sub * 2);
            }
        }

        __syncthreads();
        if (s + 2 < G2_NS) {
            load_stage(s + 2);
        } else {
            cp_commit();
        }

        // tile boundary: flush + reset (branch taken twice total)
        if ((s & 7) == 7) {
            const int tile = s >> 3;
            float* dst = Cf + (size_t)tile * BN;   // dout column offset
#pragma unroll
            for (int mt = 0; mt < 2; mt++) {
#pragma unroll
                for (int nt = 0; nt < 8; nt++) {
                    float* c = acc[mt][nt];
                    long m = m0 + wm + mt * 16 + l4;
                    long n = wn + nt * 8 + lp * 2;
                    *(float2*)(dst + m * D_OUT + n) = make_float2(c[0], c[1]);
                    *(float2*)(dst + (m + 8) * D_OUT + n) = make_float2(c[2], c[3]);
                    c[0] = c[1] = c[2] = c[3] = 0.0f;
                }
            }
        }
    }
}

// ---------------- launch ----------------
extern "C" void kernel_launch(void* const* d_in, const int* in_sizes, int n_in,
                              void* d_out, int out_size) {
    const float* x      = (const float*)d_in[0];
    const float* weight = (const float*)d_in[2];
    const float* adj    = (const float*)d_in[3];
    float* out          = (float*)d_out;

    __half *wth, *adjh, *h;
    cudaGetSymbolAddress((void**)&wth, g_wth);
    cudaGetSymbolAddress((void**)&adjh, g_adjh);
    cudaGetSymbolAddress((void**)&h, g_h);

    cudaFuncSetAttribute(gemm1_fused, cudaFuncAttributeMaxDynamicSharedMemorySize, G1_SMEM);
    cudaFuncSetAttribute(gemm2_paired, cudaFuncAttributeMaxDynamicSharedMemorySize, SMEM_TOTAL);

    cvt_small<<<128, 256>>>(adj, weight, adjh, wth);

    // GEMM1 fused: H^T = W^T @ X^T
    {
        dim3 grid(M_ALL / BN, D_OUT / BM, 1);   // (256, 2)
        gemm1_fused<<<grid, NTHREADS, G1_SMEM>>>(wth, x, h);
    }
    // GEMM2 paired: Out[b] = adj @ H_b, both dout tiles per CTA
    {
        dim3 grid(1, N_NODES / BM, N_BATCH);    // (1, 4, 64) = 256 CTAs
        gemm2_paired<<<grid, NTHREADS, SMEM_TOTAL>>>(adjh, h, out);
    }
}